// round 5
// baseline (speedup 1.0000x reference)
#include <cuda_runtime.h>
#include <cuda_bf16.h>
#include <cstdint>

#define NN   256
#define NE   1024
#define MAXC 64
#define WINF (1<<20)
#define KS   16        // FC1 K-split count
#define NT   224       // threads per block

typedef unsigned long long ull;
union F2U { float2 f; ull u; };

// ---------------- resettable state (ONE memset per replay) ----------------
struct __align__(16) Flags {
    float hidden[128 * 200];   // FC1 atomic accumulators (needs zero)
    int   done[NN * 64];       // (neuron, batch-pair) completion flags
    int   hcnt[2];             // FC1 tile counters per 64-batch half
    int   sched_ready;
};
__device__ Flags g_flags;

// ---------------- persistent scratch (rewritten before use) ----------------
__device__ float g_act[(size_t)NN * 128 * 784];   // [n][b][p]
__device__ int   g_fin[NN * MAXC];
__device__ int   g_fcc[NN * MAXC];
__device__ int   g_fdeg[NN];
__device__ int   g_order[NN];
__device__ int   g_ntasks;

#define FMA2(d, a, b) \
    asm("fma.rn.f32x2 %0, %1, %2, %0;" : "+l"(d) : "l"(a), "l"(b))

__device__ __forceinline__ int ldacq(const int* p) {
    int v; asm volatile("ld.acquire.gpu.global.b32 %0, [%1];" : "=r"(v) : "l"(p) : "memory");
    return v;
}
__device__ __forceinline__ void spinf(const int* p) {
    if (ldacq(p)) return;
    while (!ldacq(p)) __nanosleep(20);
}

// ---------------- shared memory union ----------------
struct SchedSM { int src[NE], tgt[NE], wave[NN], need[NN], list[NN]; int chg, cnt; };
struct ConvSM  { ull img[2][1056]; ull wk2[18 * 25]; };   // 32 rows x 33 ull (2 batches packed)
struct FCSM    { float w[16][74]; float2 a[16][66]; };
union  SMU { SchedSM sch; ConvSM cv; FCSM fc; };

// stage one channel (2 batches packed in ull) — conflict-free STS.64
__device__ __forceinline__ void stage2(ull* imgU, const float* sp, int tid) {
    if (tid < 196) {
        const int col  = tid % 28;
        const int rowg = tid / 28;            // 0..6 -> rows rowg*4..+3
        const float* p0 = sp + rowg * 4 * 28 + col;
        const float* p1 = p0 + 784;
        ull* d = imgU + (rowg * 4 + 2) * 33 + col + 2;
#pragma unroll
        for (int r = 0; r < 4; ++r) {
            F2U u; u.f = make_float2(__ldg(p0 + r * 28), __ldg(p1 + r * 28));
            d[r * 33] = u.u;
        }
    }
}

// 4px x 2batch packed conv: 40 LDS.64 + 100 FFMA2 per channel per thread
__device__ __forceinline__ void conv4(const ull* imb, const ull* w2, ull acc[4]) {
#pragma unroll
    for (int dy = 0; dy < 5; ++dy) {
        const ull* rp = imb + dy * 33;
        ull v[8];
#pragma unroll
        for (int j = 0; j < 8; ++j) v[j] = rp[j];
#pragma unroll
        for (int dx = 0; dx < 5; ++dx) {
            ull wv = w2[dy * 5 + dx];
#pragma unroll
            for (int o = 0; o < 4; ++o) FMA2(acc[o], wv, v[dx + o]);
        }
    }
}

__device__ __forceinline__ void store4(ull acc[4], float* d0) {
    F2U u0, u1, u2, u3;
    u0.u = acc[0]; u1.u = acc[1]; u2.u = acc[2]; u3.u = acc[3];
    float4 o0 = make_float4(fmaxf(u0.f.x, 0.f), fmaxf(u1.f.x, 0.f),
                            fmaxf(u2.f.x, 0.f), fmaxf(u3.f.x, 0.f));
    float4 o1 = make_float4(fmaxf(u0.f.y, 0.f), fmaxf(u1.f.y, 0.f),
                            fmaxf(u2.f.y, 0.f), fmaxf(u3.f.y, 0.f));
    *(float4*)d0         = o0;
    *(float4*)(d0 + 784) = o1;
}

// =====================================================================
// single persistent kernel
// =====================================================================
__global__ void __launch_bounds__(NT) net_kernel(
    const float* __restrict__ x,
    const int* __restrict__ src, const int* __restrict__ tgt,
    const float* __restrict__ conv_w, const float* __restrict__ conv_b,
    const float* __restrict__ fc1_w,  const float* __restrict__ fc1_b,
    const float* __restrict__ fc2_w,  const float* __restrict__ fc2_b,
    float* __restrict__ out, int cmax, int fcK, int nb)
{
    __shared__ SMU sm;
    const int tid = threadIdx.x;
    const int bid = blockIdx.x;

    // ================= block 0: scheduler only =================
    if (bid == 0) {
        for (int i = tid; i < NE; i += NT) { sm.sch.src[i] = src[i]; sm.sch.tgt[i] = tgt[i]; }
        for (int i = tid; i < NN; i += NT) { sm.sch.wave[i] = (i == 0) ? 0 : WINF; sm.sch.need[i] = 0; }
        if (tid == 0) { sm.sch.chg = 0; sm.sch.cnt = 0; }
        __syncthreads();

        for (int pass = 0; pass < 300; ++pass) {
            for (int e = tid; e < NE; e += NT) {
                int ws = sm.sch.wave[sm.sch.src[e]];
                if (ws + 1 < sm.sch.wave[sm.sch.tgt[e]]) {
                    atomicMin(&sm.sch.wave[sm.sch.tgt[e]], ws + 1); sm.sch.chg = 1;
                }
            }
            __syncthreads();
            int c = sm.sch.chg; __syncthreads();
            if (tid == 0) sm.sch.chg = 0;
            __syncthreads();
            if (!c) break;
        }

        if (tid == 0) sm.sch.need[255] = 1;
        __syncthreads();
        for (int pass = 0; pass < 300; ++pass) {
            for (int e = tid; e < NE; e += NT) {
                int s = sm.sch.src[e], t = sm.sch.tgt[e];
                if (sm.sch.need[t] && sm.sch.wave[s] < sm.sch.wave[t] && !sm.sch.need[s]) {
                    sm.sch.need[s] = 1; sm.sch.chg = 1;
                }
            }
            __syncthreads();
            int c = sm.sch.chg; __syncthreads();
            if (tid == 0) sm.sch.chg = 0;
            __syncthreads();
            if (!c) break;
        }

        for (int n = tid; n < NN; n += NT) {
            if (n != 0 && n != 255 && sm.sch.need[n]) {
                int r = 0;
                for (int m = 1; m < NN - 1; ++m)
                    if (sm.sch.need[m] && (sm.sch.wave[m] < sm.sch.wave[n] ||
                        (sm.sch.wave[m] == sm.sch.wave[n] && m < n))) r++;
                sm.sch.list[r] = n;
                atomicAdd(&sm.sch.cnt, 1);
            }
        }
        __syncthreads();
        const int total = sm.sch.cnt;

        {   // filtered in-lists via warp ballots (fcc = original channel rank)
            const int w7 = tid >> 5, lane = tid & 31;
            for (int ni = w7; ni <= total; ni += 7) {
                int n  = (ni == total) ? 255 : sm.sch.list[ni];
                int wn = sm.sch.wave[n];
                int cbase = 0, cnt = 0;
                for (int ch = 0; ch < NE; ch += 32) {
                    int e = ch + lane;
                    int te = sm.sch.tgt[e], se = sm.sch.src[e];
                    unsigned m_all  = __ballot_sync(0xffffffffu, te == n);
                    unsigned m_keep = __ballot_sync(0xffffffffu, te == n && sm.sch.wave[se] < wn);
                    if (m_keep & (1u << lane)) {
                        int c   = cbase + __popc(m_all  & ((1u << lane) - 1));
                        int pos = cnt   + __popc(m_keep & ((1u << lane) - 1));
                        if (pos < MAXC) { g_fin[n * MAXC + pos] = se; g_fcc[n * MAXC + pos] = c; }
                    }
                    cbase += __popc(m_all);
                    cnt   += __popc(m_keep);
                }
                if (lane == 0) g_fdeg[n] = cnt < MAXC ? cnt : MAXC;
            }
        }
        __syncthreads();

        // sort each in-list by (input wave, original rank): late producers last
        for (int idx = tid; idx <= total; idx += NT) {
            int n = (idx == total) ? 255 : sm.sch.list[idx];
            int C = g_fdeg[n];
            int* fi = g_fin + n * MAXC;
            int* fo = g_fcc + n * MAXC;
            for (int i = 0; i < C - 1; ++i) {
                int best = i, bk = sm.sch.wave[fi[i]] * 4096 + fo[i];
                for (int j = i + 1; j < C; ++j) {
                    int k = sm.sch.wave[fi[j]] * 4096 + fo[j];
                    if (k < bk) { bk = k; best = j; }
                }
                if (best != i) {
                    int a = fi[i]; fi[i] = fi[best]; fi[best] = a;
                    int b = fo[i]; fo[i] = fo[best]; fo[best] = b;
                }
            }
        }
        for (int i = tid; i < total; i += NT) g_order[i] = sm.sch.list[i];
        if (tid == 0) g_ntasks = total * 64;
        __threadfence();
        __syncthreads();
        if (tid == 0) *(volatile int*)&g_flags.sched_ready = 1;
        return;
    }

    // ================= worker blocks =================
    for (int i = tid; i < 2 * 1056; i += NT) ((ull*)sm.cv.img)[i] = 0ull;
    const int yy  = tid / 7;           // valid for tid<196
    const int xx0 = (tid % 7) * 4;
    __syncthreads();

    // ---- wave 0: neuron 0 from x ----
    {
        if (tid < 25) { F2U u; float w = conv_w[tid]; u.f = make_float2(w, w); sm.cv.wk2[tid] = u.u; }
        const float bias = conv_b[0];
        for (int t = bid - 1; t < 64; t += nb - 1) {
            stage2(sm.cv.img[0], x + (size_t)t * 1568, tid);
            __syncthreads();
            if (tid < 196) {
                ull acc[4];
                F2U b2; b2.f = make_float2(bias, bias);
#pragma unroll
                for (int o = 0; o < 4; ++o) acc[o] = b2.u;
                conv4(sm.cv.img[0] + yy * 33 + xx0, sm.cv.wk2, acc);
                store4(acc, g_act + (size_t)(t * 2) * 784 + yy * 28 + xx0);
            }
            __threadfence();
            __syncthreads();
            if (tid == 0) *(volatile int*)&g_flags.done[t] = 1;
        }
    }

    // ---- wait for schedule ----
    spinf(&g_flags.sched_ready);
    __syncthreads();

    const int ntasks  = g_ntasks;
    const int fdeg255 = g_fdeg[255];

    // ---- dataflow conv tasks (inputs sorted by wave; JIT per-channel gate) ----
    for (int t = bid - 1; t < ntasks; t += nb - 1) {
        const int ni = t >> 6;
        const int pb = t & 63;
        const int n  = g_order[ni];
        const int C  = g_fdeg[n];
        const int* fin = g_fin + n * MAXC;
        const int* fcc = g_fcc + n * MAXC;
        const float* wbase = conv_w + (size_t)n * cmax * 25;

        const int CW = C < 16 ? C : 16;
        for (int i = tid; i < CW * 25; i += NT) {      // weight prefetch (dep-free)
            int c = i / 25, r = i - c * 25;
            F2U u; float w = wbase[fcc[c] * 25 + r];
            u.f = make_float2(w, w);
            sm.cv.wk2[c * 25 + r] = u.u;
        }

        spinf(&g_flags.done[fin[0] * 64 + pb]);        // earliest producer first
        stage2(sm.cv.img[0], g_act + ((size_t)fin[0] * 128 + pb * 2) * 784, tid);
        __syncthreads();

        ull acc[4];
        { F2U b2; float b = conv_b[n]; b2.f = make_float2(b, b);
#pragma unroll
          for (int o = 0; o < 4; ++o) acc[o] = b2.u; }

        for (int c = 0; c < C; ++c) {
            const int buf = c & 1;
            if (c + 1 < C) {
                spinf(&g_flags.done[fin[c + 1] * 64 + pb]);   // JIT gate
                stage2(sm.cv.img[buf ^ 1],
                       g_act + ((size_t)fin[c + 1] * 128 + pb * 2) * 784, tid);
                if (c + 1 >= 16 && tid < 25) {
                    F2U u; float w = wbase[fcc[c + 1] * 25 + tid];
                    u.f = make_float2(w, w);
                    sm.cv.wk2[(16 + ((c + 1) & 1)) * 25 + tid] = u.u;
                }
            }
            if (tid < 196) {
                const ull* w2 = sm.cv.wk2 + ((c < 16) ? c : (16 + (c & 1))) * 25;
                conv4(sm.cv.img[buf] + yy * 33 + xx0, w2, acc);
            }
            __syncthreads();
        }
        if (tid < 196)
            store4(acc, g_act + ((size_t)n * 128 + pb * 2) * 784 + yy * 28 + xx0);
        __threadfence();
        __syncthreads();
        if (tid == 0) *(volatile int*)&g_flags.done[n * 64 + pb] = 1;
    }

    // ---- FC1 block tasks: 8 tiles (4 h x 2 b-halves) x KS k-splits ----
    {
        const int Kc = fdeg255 * 49;
        const int* fin = g_fin + 255 * MAXC;
        const int* fcc = g_fcc + 255 * MAXC;
        for (int t = bid - 1; t < 8 * KS; t += nb - 1) {
            const int tile = t / KS;
            const int ks   = t - tile * KS;
            const int h0   = (tile >> 1) * 64;
            const int b0   = (tile & 1) * 64;

            for (int i = tid; i < fdeg255 * 32; i += NT)
                spinf(&g_flags.done[fin[i >> 5] * 64 + (b0 >> 1) + (i & 31)]);
            __syncthreads();

            const int hg = tid >> 4;     // tid<128: 8 h each
            const int bg = tid & 15;     // 4 b each
            ull acc[4][4];
#pragma unroll
            for (int i = 0; i < 4; ++i)
#pragma unroll
                for (int j = 0; j < 4; ++j) acc[i][j] = 0ull;

            for (int kidx = ks; kidx < Kc; kidx += KS) {
                const int c  = kidx / 49;
                const int p0 = (kidx - c * 49) * 16;
                const float* wrow = fc1_w + (size_t)fcc[c] * 784 + p0;
                const float* arow = g_act + ((size_t)fin[c] * 128 + b0) * 784 + p0;
                for (int q = tid; q < 256; q += NT) {       // stage weights 64h x 16k
                    int row = q >> 2, c4 = q & 3;
                    int h = h0 + row;
                    float4 v = (h < 200) ? *(const float4*)(wrow + (size_t)h * fcK + c4 * 4)
                                         : make_float4(0.f, 0.f, 0.f, 0.f);
                    sm.fc.w[c4 * 4 + 0][row] = v.x; sm.fc.w[c4 * 4 + 1][row] = v.y;
                    sm.fc.w[c4 * 4 + 2][row] = v.z; sm.fc.w[c4 * 4 + 3][row] = v.w;
                }
                for (int q = tid; q < 256; q += NT) {       // stage acts 64b x 16k
                    int row = q >> 2, c4 = q & 3;
                    float4 v = *(const float4*)(arow + (size_t)row * 784 + c4 * 4);
                    sm.fc.a[c4 * 4 + 0][row] = make_float2(v.x, v.x);
                    sm.fc.a[c4 * 4 + 1][row] = make_float2(v.y, v.y);
                    sm.fc.a[c4 * 4 + 2][row] = make_float2(v.z, v.z);
                    sm.fc.a[c4 * 4 + 3][row] = make_float2(v.w, v.w);
                }
                __syncthreads();
                if (tid < 128) {
#pragma unroll
                    for (int k = 0; k < 16; ++k) {
                        const ull* wp  = (const ull*)&sm.fc.w[k][hg * 8];
                        const ull* ap2 = (const ull*)&sm.fc.a[k][bg * 4];
                        ull w0 = wp[0], w1 = wp[1], w2v = wp[2], w3 = wp[3];
                        ull a0 = ap2[0], a1 = ap2[1], a2 = ap2[2], a3 = ap2[3];
                        FMA2(acc[0][0], w0,  a0); FMA2(acc[0][1], w0,  a1);
                        FMA2(acc[0][2], w0,  a2); FMA2(acc[0][3], w0,  a3);
                        FMA2(acc[1][0], w1,  a0); FMA2(acc[1][1], w1,  a1);
                        FMA2(acc[1][2], w1,  a2); FMA2(acc[1][3], w1,  a3);
                        FMA2(acc[2][0], w2v, a0); FMA2(acc[2][1], w2v, a1);
                        FMA2(acc[2][2], w2v, a2); FMA2(acc[2][3], w2v, a3);
                        FMA2(acc[3][0], w3,  a0); FMA2(acc[3][1], w3,  a1);
                        FMA2(acc[3][2], w3,  a2); FMA2(acc[3][3], w3,  a3);
                    }
                }
                __syncthreads();
            }
            if (tid < 128 && h0 + hg * 8 < 200) {
#pragma unroll
                for (int i = 0; i < 4; ++i)
#pragma unroll
                    for (int j = 0; j < 4; ++j) {
                        F2U u; u.u = acc[i][j];
                        int h = h0 + hg * 8 + i * 2;
                        int b = b0 + bg * 4 + j;
                        atomicAdd(&g_flags.hidden[b * 200 + h],     u.f.x);
                        atomicAdd(&g_flags.hidden[b * 200 + h + 1], u.f.y);
                    }
            }
            __threadfence();
            __syncthreads();
            if (tid == 0) atomicAdd(&g_flags.hcnt[b0 >> 6], 1);
        }
    }

    // ---- FC2 + log_softmax: warp tasks ----
    {
        const int lane = tid & 31;
        const int gw   = (bid - 1) * 7 + (tid >> 5);
        const int strd = (nb - 1) * 7;
        for (int b = gw; b < 128; b += strd) {
            if (lane == 0) {
                const int* cc = &g_flags.hcnt[b >> 6];
                while (ldacq(cc) < 4 * KS) __nanosleep(64);
            }
            __syncwarp();
            float acc = 0.f;
            if (lane < 10) {
                acc = fc2_b[lane];
                const float* wp = fc2_w + lane * 200;
                const float* hp = g_flags.hidden + b * 200;
#pragma unroll 5
                for (int h4 = 0; h4 < 50; ++h4) {
                    float4 w  = ((const float4*)wp)[h4];
                    float4 hv = ((const float4*)hp)[h4];
                    float4 fb = ((const float4*)fc1_b)[h4];
                    acc += fmaxf(hv.x + fb.x, 0.f) * w.x + fmaxf(hv.y + fb.y, 0.f) * w.y
                         + fmaxf(hv.z + fb.z, 0.f) * w.z + fmaxf(hv.w + fb.w, 0.f) * w.w;
                }
            }
            float m = (lane < 10) ? acc : -1e30f;
#pragma unroll
            for (int off = 16; off; off >>= 1) m = fmaxf(m, __shfl_xor_sync(0xffffffffu, m, off));
            float e = (lane < 10) ? expf(acc - m) : 0.f;
            float s = e;
#pragma unroll
            for (int off = 16; off; off >>= 1) s += __shfl_xor_sync(0xffffffffu, s, off);
            const float lse = m + logf(s);
            if (lane < 10) out[b * 10 + lane] = acc - lse;
        }
    }
}

// ---------------- launch: ONE memset + ONE kernel ----------------
extern "C" void kernel_launch(void* const* d_in, const int* in_sizes, int n_in,
                              void* d_out, int out_size) {
    const float* x      = (const float*)d_in[0];
    const int*   src    = (const int*)  d_in[1];
    const int*   tgt    = (const int*)  d_in[2];
    const float* conv_w = (const float*)d_in[3];
    const float* conv_b = (const float*)d_in[4];
    const float* fc1_w  = (const float*)d_in[5];
    const float* fc1_b  = (const float*)d_in[6];
    const float* fc2_w  = (const float*)d_in[7];
    const float* fc2_b  = (const float*)d_in[8];

    const int cmax = in_sizes[3] / (NN * 25);
    const int fcK  = in_sizes[5] / 200;

    void* flagsPtr = nullptr;
    cudaGetSymbolAddress(&flagsPtr, g_flags);
    cudaMemsetAsync(flagsPtr, 0, sizeof(Flags), 0);

    int dev = 0, sms = 0, occ = 0;
    cudaGetDevice(&dev);
    cudaDeviceGetAttribute(&sms, cudaDevAttrMultiProcessorCount, dev);
    cudaOccupancyMaxActiveBlocksPerMultiprocessor(&occ, net_kernel, NT, 0);
    int nb = sms * occ;
    if (nb < 129) nb = 129;

    net_kernel<<<nb, NT>>>(x, src, tgt, conv_w, conv_b, fc1_w, fc1_b,
                           fc2_w, fc2_b, (float*)d_out, cmax, fcK, nb);
}